// round 5
// baseline (speedup 1.0000x reference)
#include <cuda_runtime.h>
#include <math.h>

#define LDIM 32
#define HDIM 64

typedef unsigned long long ull;

__device__ __forceinline__ ull pack2(float lo, float hi) {
    ull r; asm("mov.b64 %0, {%1, %2};" : "=l"(r) : "f"(lo), "f"(hi)); return r;
}
__device__ __forceinline__ float2 unpack2(ull v) {
    float2 r; asm("mov.b64 {%0, %1}, %2;" : "=f"(r.x), "=f"(r.y) : "l"(v)); return r;
}
#define FMA2(d, a, b, c) \
    asm("fma.rn.f32x2 %0, %1, %2, %3;" : "=l"(d) : "l"(a), "l"(b), "l"(c))

// TWO samples per warp (one warp per block). Thread t owns channels {t, t+32}
// of BOTH samples; the packed Wc register columns are shared between them.
// The two recurrence chains interleave in one instruction stream, filling
// each other's stall slots. Log-softmax uses only the logit difference
// d = z0 - z1 (D=2): lp = -softplus(xC ? d : -d), reduced with a single
// 5-shfl chain per sample, deferred one step to overlap the matvec.
__global__ void __launch_bounds__(32) rnn2d_kernel(
    const int*   __restrict__ x,     // (B, 32, 32) int32, values in {0,1}
    const float* __restrict__ Win,   // (2, 64)
    const float* __restrict__ Wc,    // (64, 64)
    const float* __restrict__ bc,    // (64,)
    const float* __restrict__ Wout,  // (64, 2)
    const float* __restrict__ bout,  // (2,)
    float*       __restrict__ out)   // (B,)
{
    const int b0 = blockIdx.x * 2;
    const int t  = threadIdx.x;         // 0..31

    __shared__ float2 HprevA[LDIM][LDIM];   // [col][t] thread-private entries
    __shared__ float2 HprevB[LDIM][LDIM];
    __shared__ float  ubufA[2][HDIM];       // double-buffered u (k-order)
    __shared__ float  ubufB[2][HDIM];
    __shared__ int    xrowA[2][LDIM];
    __shared__ int    xrowB[2][LDIM];

    // ---- weights (shared between the two samples) ----
    ull wcp0[HDIM / 2], wcp1[HDIM / 2];
#pragma unroll
    for (int k = 0; k < HDIM / 2; ++k) {
        wcp0[k] = pack2(Wc[(2 * k) * HDIM + t],      Wc[(2 * k + 1) * HDIM + t]);
        wcp1[k] = pack2(Wc[(2 * k) * HDIM + t + 32], Wc[(2 * k + 1) * HDIM + t + 32]);
    }
    const float win00 = Win[t],      win10 = Win[HDIM + t];
    const float win01 = Win[t + 32], win11 = Win[HDIM + t + 32];
    const float bc0   = bc[t],       bc1   = bc[t + 32];
    const float wod0  = Wout[t * 2]        - Wout[t * 2 + 1];         // wo0 - wo1
    const float wod1  = Wout[(t + 32) * 2] - Wout[(t + 32) * 2 + 1];
    const float bod   = bout[0] - bout[1];

#pragma unroll
    for (int c = 0; c < LDIM; ++c) {
        HprevA[c][t] = make_float2(0.0f, 0.0f);
        HprevB[c][t] = make_float2(0.0f, 0.0f);
    }

    const int* xbA = x + (size_t)b0 * LDIM * LDIM;
    const int* xbB = xbA + LDIM * LDIM;

    float logpA = 0.0f, logpB = 0.0f;
    float pdA = 0.0f, pdB = 0.0f;       // deferred per-thread d-partials
    int   pxA = 0,    pxB = 0;
    float pend = 0.0f;                  // 0 until first step pending
    float2 hpA = make_float2(0.0f, 0.0f);
    float2 hpB = make_float2(0.0f, 0.0f);

    for (int i = 0; i < LDIM; ++i) {
        __syncwarp();
        xrowA[i & 1][t] = xbA[i * LDIM + t];
        xrowB[i & 1][t] = xbB[i * LDIM + t];

        const int dir  = (i & 1) ? -1 : 1;
        const int cur  = i & 1;
        const int prev = cur ^ 1;

        float hA0 = 0.0f, hA1 = 0.0f;
        float hB0 = 0.0f, hB1 = 0.0f;
        int   xLA = 0, xLB = 0;

#pragma unroll 2
        for (int jj = 0; jj < LDIM; ++jj) {
            const int c = (i & 1) ? (LDIM - 1 - jj) : jj;
            const int p = jj & 1;

            // ---- pre-barrier: stage u for both samples ----
            const float uA0 = hA0 + hpA.x, uA1 = hA1 + hpA.y;
            const float uB0 = hB0 + hpB.x, uB1 = hB1 + hpB.y;
            ubufA[p][t] = uA0;  ubufA[p][t + 32] = uA1;
            ubufB[p][t] = uB0;  ubufB[p][t + 32] = uB1;

            // base terms (read stable xrow[prev] / register xL — off chain)
            float rA0 = bc0, rA1 = bc1, rB0 = bc0, rB1 = bc1;
            if (jj > 0) {
                rA0 += xLA ? win10 : win00;  rA1 += xLA ? win11 : win01;
                rB0 += xLB ? win10 : win00;  rB1 += xLB ? win11 : win01;
            }
            if (i > 0) {
                const int xUA = xrowA[prev][c], xUB = xrowB[prev][c];
                rA0 += xUA ? win10 : win00;  rA1 += xUA ? win11 : win01;
                rB0 += xUB ? win10 : win00;  rB1 += xUB ? win11 : win01;
            }

            __syncwarp();

            // ---- deferred d-reductions of step j-1 (overlap the matvecs) ----
            float dA = pdA, dB = pdB;
#pragma unroll
            for (int off = 16; off > 0; off >>= 1) {
                dA += __shfl_xor_sync(0xffffffffu, dA, off);
                dB += __shfl_xor_sync(0xffffffffu, dB, off);
            }
            {
                const float vA = pxA ? dA : -dA;   // z_uns - z_sel
                const float vB = pxB ? dB : -dB;
                float lpA = -(fmaxf(vA, 0.0f) + __logf(1.0f + __expf(-fabsf(vA))));
                float lpB = -(fmaxf(vB, 0.0f) + __logf(1.0f + __expf(-fabsf(vB))));
                if (lpA != lpA) lpA = -35.0f;
                if (lpB != lpB) lpB = -35.0f;
                logpA += pend * lpA;
                logpB += pend * lpB;
            }

            // ---- two interleaved 64-wide matvecs (shared Wc registers) ----
            ull aA0 = pack2(rA0, 0.0f), aA1 = pack2(rA1, 0.0f);
            ull aB0 = pack2(rB0, 0.0f), aB1 = pack2(rB1, 0.0f);
            ull aA2 = 0, aA3 = 0, aB2 = 0, aB3 = 0;
            const ulonglong2* upA = (const ulonglong2*)ubufA[p];
            const ulonglong2* upB = (const ulonglong2*)ubufB[p];
#pragma unroll
            for (int k = 0; k < HDIM / 4; ++k) {
                const ulonglong2 uvA = upA[k];
                const ulonglong2 uvB = upB[k];
                FMA2(aA0, uvA.x, wcp0[2 * k],     aA0);
                FMA2(aB0, uvB.x, wcp0[2 * k],     aB0);
                FMA2(aA1, uvA.x, wcp1[2 * k],     aA1);
                FMA2(aB1, uvB.x, wcp1[2 * k],     aB1);
                FMA2(aA2, uvA.y, wcp0[2 * k + 1], aA2);
                FMA2(aB2, uvB.y, wcp0[2 * k + 1], aB2);
                FMA2(aA3, uvA.y, wcp1[2 * k + 1], aA3);
                FMA2(aB3, uvB.y, wcp1[2 * k + 1], aB3);
            }
            const float2 fA0 = unpack2(aA0), fA2 = unpack2(aA2);
            const float2 fA1 = unpack2(aA1), fA3 = unpack2(aA3);
            const float2 fB0 = unpack2(aB0), fB2 = unpack2(aB2);
            const float2 fB1 = unpack2(aB1), fB3 = unpack2(aB3);
            const float sA0 = (fA0.x + fA0.y) + (fA2.x + fA2.y);
            const float sA1 = (fA1.x + fA1.y) + (fA3.x + fA3.y);
            const float sB0 = (fB0.x + fB0.y) + (fB2.x + fB2.y);
            const float sB1 = (fB1.x + fB1.y) + (fB3.x + fB3.y);

            // elu (alpha = 1)
            const float nA0 = (sA0 > 0.0f) ? sA0 : (__expf(sA0) - 1.0f);
            const float nA1 = (sA1 > 0.0f) ? sA1 : (__expf(sA1) - 1.0f);
            const float nB0 = (sB0 > 0.0f) ? sB0 : (__expf(sB0) - 1.0f);
            const float nB1 = (sB1 > 0.0f) ? sB1 : (__expf(sB1) - 1.0f);

            // ---- stash this step's d-partials (d = z0 - z1) ----
            pdA = nA0 * wod0 + nA1 * wod1 + (t == 0 ? bod : 0.0f);
            pdB = nB0 * wod0 + nB1 * wod1 + (t == 0 ? bod : 0.0f);
            pxA = xrowA[cur][c];
            pxB = xrowB[cur][c];
            pend = 1.0f;

            // writeback + prefetch next carry-from-above (thread-private)
            HprevA[c][t] = make_float2(nA0, nA1);
            HprevB[c][t] = make_float2(nB0, nB1);
            const int cn = (jj < LDIM - 1) ? (c + dir) : c;
            hpA = HprevA[cn][t];
            hpB = HprevB[cn][t];

            hA0 = nA0; hA1 = nA1;
            hB0 = nB0; hB1 = nB1;
            xLA = pxA; xLB = pxB;
        }
    }

    // ---- flush the final pending step ----
    {
        float dA = pdA, dB = pdB;
#pragma unroll
        for (int off = 16; off > 0; off >>= 1) {
            dA += __shfl_xor_sync(0xffffffffu, dA, off);
            dB += __shfl_xor_sync(0xffffffffu, dB, off);
        }
        const float vA = pxA ? dA : -dA;
        const float vB = pxB ? dB : -dB;
        float lpA = -(fmaxf(vA, 0.0f) + __logf(1.0f + __expf(-fabsf(vA))));
        float lpB = -(fmaxf(vB, 0.0f) + __logf(1.0f + __expf(-fabsf(vB))));
        if (lpA != lpA) lpA = -35.0f;
        if (lpB != lpB) lpB = -35.0f;
        logpA += lpA;
        logpB += lpB;
    }

    if (t == 0) {
        out[b0]     = 0.5f * logpA;
        out[b0 + 1] = 0.5f * logpB;
    }
}

extern "C" void kernel_launch(void* const* d_in, const int* in_sizes, int n_in,
                              void* d_out, int out_size) {
    const int*   x    = (const int*)  d_in[0];
    const float* Win  = (const float*)d_in[1];
    const float* Wc   = (const float*)d_in[2];
    const float* bc   = (const float*)d_in[3];
    const float* Wout = (const float*)d_in[4];
    const float* bout = (const float*)d_in[5];
    float* out = (float*)d_out;

    const int B = in_sizes[0] / (LDIM * LDIM);
    rnn2d_kernel<<<B / 2, 32>>>(x, Win, Wc, bc, Wout, bout, out);
}

// round 6
// speedup vs baseline: 1.8351x; 1.8351x over previous
#include <cuda_runtime.h>
#include <math.h>

#define LDIM 32
#define HDIM 64

typedef unsigned long long ull;

__device__ __forceinline__ ull pack2(float lo, float hi) {
    ull r; asm("mov.b64 %0, {%1, %2};" : "=l"(r) : "f"(lo), "f"(hi)); return r;
}
__device__ __forceinline__ float2 unpack2(ull v) {
    float2 r; asm("mov.b64 {%0, %1}, %2;" : "=f"(r.x), "=f"(r.y) : "l"(v)); return r;
}
#define FMA2(d, a, b, c) \
    asm("fma.rn.f32x2 %0, %1, %2, %3;" : "=l"(d) : "l"(a), "l"(b), "l"(c))

// One warp per sample. Thread t owns ADJACENT channels {2t, 2t+1}, so its
// u-pair is one packed 64-bit register. The matvec broadcast is done with
// register shuffles (32 × 64-bit lane broadcasts) — no shared-memory staging
// and NO barriers anywhere in the hot loop. Hprev (carry-from-above) is
// thread-private smem, prefetched one step ahead. Log-softmax uses the D=2
// logit difference: lp = -softplus(±d), 5 shfls, deferred one step.
__global__ void __launch_bounds__(32) rnn2d_kernel(
    const int*   __restrict__ x,     // (B, 32, 32) int32, values in {0,1}
    const float* __restrict__ Win,   // (2, 64)
    const float* __restrict__ Wc,    // (64, 64)
    const float* __restrict__ bc,    // (64,)
    const float* __restrict__ Wout,  // (64, 2)
    const float* __restrict__ bout,  // (2,)
    float*       __restrict__ out)   // (B,)
{
    const int b  = blockIdx.x;
    const int t  = threadIdx.x;         // 0..31
    const int c0 = 2 * t, c1 = 2 * t + 1;

    __shared__ float2 Hprev[LDIM][LDIM];   // [col][t] — strictly thread-private

    // ---- weights: wA[k] = (Wc[2k][c0], Wc[2k+1][c0]); wB for c1 ----
    ull wA[HDIM / 2], wB[HDIM / 2];
#pragma unroll
    for (int k = 0; k < HDIM / 2; ++k) {
        wA[k] = pack2(Wc[(2 * k) * HDIM + c0], Wc[(2 * k + 1) * HDIM + c0]);
        wB[k] = pack2(Wc[(2 * k) * HDIM + c1], Wc[(2 * k + 1) * HDIM + c1]);
    }
    const float win00 = Win[c0], win10 = Win[HDIM + c0];
    const float win01 = Win[c1], win11 = Win[HDIM + c1];
    const float bc0   = bc[c0],  bc1   = bc[c1];
    const float wod0  = Wout[c0 * 2] - Wout[c0 * 2 + 1];   // wo(:,0)-wo(:,1)
    const float wod1  = Wout[c1 * 2] - Wout[c1 * 2 + 1];
    const float bodt  = (t == 0) ? (bout[0] - bout[1]) : 0.0f;

#pragma unroll
    for (int c = 0; c < LDIM; ++c) Hprev[c][t] = make_float2(0.0f, 0.0f);

    const int* xb = x + (size_t)b * LDIM * LDIM;

    float logp = 0.0f;
    float pd   = 0.0f;      // deferred per-thread d-partial (d = z0 - z1)
    int   px   = 0;
    float pend = 0.0f;
    float2 hp  = make_float2(0.0f, 0.0f);
    int xvPrev = 0;

    for (int i = 0; i < LDIM; ++i) {
        const int xv  = xb[i * LDIM + t];   // this thread's column value, row i
        const int dir = (i & 1) ? -1 : 1;

        float h0 = 0.0f, h1 = 0.0f;
        int   xL = 0;

#pragma unroll 2
        for (int jj = 0; jj < LDIM; ++jj) {
            const int c = (i & 1) ? (LDIM - 1 - jj) : jj;

            // u = h + carry-from-above (hp prefetched); pack the owned pair
            const float u0 = h0 + hp.x;
            const float u1 = h1 + hp.y;
            const ull   ud = pack2(u0, u1);

            // base = bc + newR @ Win (off the recurrence chain)
            float r0 = bc0, r1 = bc1;
            if (jj > 0) { r0 += xL ? win10 : win00;  r1 += xL ? win11 : win01; }
            if (i  > 0) {
                const int xU = __shfl_sync(0xffffffffu, xvPrev, c);
                r0 += xU ? win10 : win00;  r1 += xU ? win11 : win01;
            }

            // ---- deferred softmax of step j-1 (overlaps the matvec) ----
            float d = pd;
#pragma unroll
            for (int off = 16; off > 0; off >>= 1)
                d += __shfl_xor_sync(0xffffffffu, d, off);
            {
                const float v  = px ? d : -d;
                float lp = -(fmaxf(v, 0.0f) + __logf(1.0f + __expf(-fabsf(v))));
                if (lp != lp) lp = -35.0f;
                logp += pend * lp;
            }

            // ---- matvec via register shuffles: 32 × 64-bit broadcasts ----
            ull a0e = pack2(r0, 0.0f), a0o = 0;
            ull a1e = pack2(r1, 0.0f), a1o = 0;
#pragma unroll
            for (int k = 0; k < 32; k += 2) {
                const ull uk0 = __shfl_sync(0xffffffffu, ud, k);
                const ull uk1 = __shfl_sync(0xffffffffu, ud, k + 1);
                FMA2(a0e, uk0, wA[k],     a0e);
                FMA2(a1e, uk0, wB[k],     a1e);
                FMA2(a0o, uk1, wA[k + 1], a0o);
                FMA2(a1o, uk1, wB[k + 1], a1o);
            }
            const float2 f0e = unpack2(a0e), f0o = unpack2(a0o);
            const float2 f1e = unpack2(a1e), f1o = unpack2(a1o);
            const float s0 = (f0e.x + f0e.y) + (f0o.x + f0o.y);
            const float s1 = (f1e.x + f1e.y) + (f1o.x + f1o.y);

            // elu (alpha = 1)
            const float nh0 = (s0 > 0.0f) ? s0 : (__expf(s0) - 1.0f);
            const float nh1 = (s1 > 0.0f) ? s1 : (__expf(s1) - 1.0f);

            // ---- stash this step's softmax inputs ----
            px   = __shfl_sync(0xffffffffu, xv, c);
            pd   = nh0 * wod0 + nh1 * wod1 + bodt;
            pend = 1.0f;

            // writeback + prefetch next carry-from-above (thread-private smem)
            Hprev[c][t] = make_float2(nh0, nh1);
            const int cn = (jj < LDIM - 1) ? (c + dir) : c;  // next row: same col
            hp = Hprev[cn][t];

            h0 = nh0;
            h1 = nh1;
            xL = px;
        }
        xvPrev = xv;
    }

    // ---- flush the final pending step ----
    {
        float d = pd;
#pragma unroll
        for (int off = 16; off > 0; off >>= 1)
            d += __shfl_xor_sync(0xffffffffu, d, off);
        const float v  = px ? d : -d;
        float lp = -(fmaxf(v, 0.0f) + __logf(1.0f + __expf(-fabsf(v))));
        if (lp != lp) lp = -35.0f;
        logp += pend * lp;
    }

    if (t == 0) out[b] = 0.5f * logp;
}

extern "C" void kernel_launch(void* const* d_in, const int* in_sizes, int n_in,
                              void* d_out, int out_size) {
    const int*   x    = (const int*)  d_in[0];
    const float* Win  = (const float*)d_in[1];
    const float* Wc   = (const float*)d_in[2];
    const float* bc   = (const float*)d_in[3];
    const float* Wout = (const float*)d_in[4];
    const float* bout = (const float*)d_in[5];
    float* out = (float*)d_out;

    const int B = in_sizes[0] / (LDIM * LDIM);
    rnn2d_kernel<<<B, 32>>>(x, Win, Wc, bc, Wout, bout, out);
}

// round 7
// speedup vs baseline: 1.8830x; 1.0261x over previous
#include <cuda_runtime.h>
#include <math.h>

#define LDIM 32
#define HDIM 64

typedef unsigned long long ull;

__device__ __forceinline__ ull pack2(float lo, float hi) {
    ull r; asm("mov.b64 %0, {%1, %2};" : "=l"(r) : "f"(lo), "f"(hi)); return r;
}
__device__ __forceinline__ float2 unpack2(ull v) {
    float2 r; asm("mov.b64 {%0, %1}, %2;" : "=f"(r.x), "=f"(r.y) : "l"(v)); return r;
}
#define FMA2(d, a, b, c) \
    asm("fma.rn.f32x2 %0, %1, %2, %3;" : "=l"(d) : "l"(a), "l"(b), "l"(c))

// One warp per sample. Thread t owns channels {t, t+32} (R2 layout).
// u broadcast via double-buffered smem (2 STS + 16 broadcast LDS.128),
// ONE syncwarp per step. x rows live in registers (broadcast by shfl),
// next row's x prefetched a row early. Log-softmax uses the D=2 logit
// difference d = z0-z1: lp = -softplus(xC ? d : -d), a single 5-shfl
// reduction deferred one step to overlap the matvec.
__global__ void __launch_bounds__(32) rnn2d_kernel(
    const int*   __restrict__ x,     // (B, 32, 32) int32, values in {0,1}
    const float* __restrict__ Win,   // (2, 64)
    const float* __restrict__ Wc,    // (64, 64)
    const float* __restrict__ bc,    // (64,)
    const float* __restrict__ Wout,  // (64, 2)
    const float* __restrict__ bout,  // (2,)
    float*       __restrict__ out)   // (B,)
{
    const int b = blockIdx.x;
    const int t = threadIdx.x;          // 0..31

    __shared__ float2 Hprev2[LDIM][LDIM];           // [col][t] thread-private
    __shared__ __align__(16) float ubuf[2][HDIM];   // double-buffered u (k-order)

    // ---- weights: columns j0=t, j1=t+32 packed along k ----
    ull wcp0[HDIM / 2], wcp1[HDIM / 2];
#pragma unroll
    for (int k = 0; k < HDIM / 2; ++k) {
        wcp0[k] = pack2(Wc[(2 * k) * HDIM + t],      Wc[(2 * k + 1) * HDIM + t]);
        wcp1[k] = pack2(Wc[(2 * k) * HDIM + t + 32], Wc[(2 * k + 1) * HDIM + t + 32]);
    }
    const float win00 = Win[t],      win10 = Win[HDIM + t];
    const float win01 = Win[t + 32], win11 = Win[HDIM + t + 32];
    const float bc0   = bc[t],       bc1   = bc[t + 32];
    const float wod0  = Wout[t * 2]        - Wout[t * 2 + 1];
    const float wod1  = Wout[(t + 32) * 2] - Wout[(t + 32) * 2 + 1];
    const float bodt  = (t == 0) ? (bout[0] - bout[1]) : 0.0f;

#pragma unroll
    for (int c = 0; c < LDIM; ++c) Hprev2[c][t] = make_float2(0.0f, 0.0f);

    const int* xb = x + (size_t)b * LDIM * LDIM;

    float logp = 0.0f;
    float pd   = 0.0f;                  // deferred d-partial (d = z0 - z1)
    int   px   = 0;
    float pend = 0.0f;
    float2 hp  = make_float2(0.0f, 0.0f);

    int xv     = xb[t];                 // row 0 (this thread's column)
    int xvPrev = 0;

    for (int i = 0; i < LDIM; ++i) {
        const int xvNext = xb[((i < LDIM - 1) ? (i + 1) : (LDIM - 1)) * LDIM + t];
        const int dir = (i & 1) ? -1 : 1;

        float h0 = 0.0f, h1 = 0.0f;
        int   xL = 0;

#pragma unroll 4
        for (int jj = 0; jj < LDIM; ++jj) {
            const int c = (i & 1) ? (LDIM - 1 - jj) : jj;
            const int p = jj & 1;

            // stage u = h + carry-from-above (hp prefetched, thread-private)
            ubuf[p][t]      = h0 + hp.x;
            ubuf[p][t + 32] = h1 + hp.y;

            // base = bc + newR @ Win (off the recurrence chain)
            float r0 = bc0, r1 = bc1;
            if (jj > 0) { r0 += xL ? win10 : win00;  r1 += xL ? win11 : win01; }
            if (i  > 0) {
                const int xU = __shfl_sync(0xffffffffu, xvPrev, c);
                r0 += xU ? win10 : win00;  r1 += xU ? win11 : win01;
            }

            __syncwarp();

            // ---- deferred softmax of step j-1 (overlaps the matvec) ----
            float d = pd;
#pragma unroll
            for (int off = 16; off > 0; off >>= 1)
                d += __shfl_xor_sync(0xffffffffu, d, off);
            {
                const float v = px ? d : -d;
                float lp = -(fmaxf(v, 0.0f) + __logf(1.0f + __expf(-fabsf(v))));
                if (lp != lp) lp = -35.0f;
                logp += pend * lp;
            }

            // ---- 64-wide matvec, packed f32x2 FMAs ----
            ull a00 = pack2(r0, 0.0f), a01 = 0;
            ull a10 = pack2(r1, 0.0f), a11 = 0;
            const ulonglong2* up = (const ulonglong2*)ubuf[p];
#pragma unroll
            for (int k = 0; k < HDIM / 4; ++k) {
                const ulonglong2 uv = up[k];
                FMA2(a00, uv.x, wcp0[2 * k],     a00);
                FMA2(a10, uv.x, wcp1[2 * k],     a10);
                FMA2(a01, uv.y, wcp0[2 * k + 1], a01);
                FMA2(a11, uv.y, wcp1[2 * k + 1], a11);
            }
            const float2 f00 = unpack2(a00), f01 = unpack2(a01);
            const float2 f10 = unpack2(a10), f11 = unpack2(a11);
            const float s0 = (f00.x + f00.y) + (f01.x + f01.y);
            const float s1 = (f10.x + f10.y) + (f11.x + f11.y);

            // elu (alpha = 1)
            const float nh0 = (s0 > 0.0f) ? s0 : (__expf(s0) - 1.0f);
            const float nh1 = (s1 > 0.0f) ? s1 : (__expf(s1) - 1.0f);

            // ---- stash this step's softmax inputs ----
            px   = __shfl_sync(0xffffffffu, xv, c);
            pd   = nh0 * wod0 + nh1 * wod1 + bodt;
            pend = 1.0f;

            // writeback + prefetch next carry-from-above (thread-private)
            Hprev2[c][t] = make_float2(nh0, nh1);
            const int cn = (jj < LDIM - 1) ? (c + dir) : c;  // next row: same col
            hp = Hprev2[cn][t];

            h0 = nh0;
            h1 = nh1;
            xL = px;
        }

        xvPrev = xv;
        xv     = xvNext;
    }

    // ---- flush the final pending step ----
    {
        float d = pd;
#pragma unroll
        for (int off = 16; off > 0; off >>= 1)
            d += __shfl_xor_sync(0xffffffffu, d, off);
        const float v = px ? d : -d;
        float lp = -(fmaxf(v, 0.0f) + __logf(1.0f + __expf(-fabsf(v))));
        if (lp != lp) lp = -35.0f;
        logp += pend * lp;
    }

    if (t == 0) out[b] = 0.5f * logp;
}

extern "C" void kernel_launch(void* const* d_in, const int* in_sizes, int n_in,
                              void* d_out, int out_size) {
    const int*   x    = (const int*)  d_in[0];
    const float* Win  = (const float*)d_in[1];
    const float* Wc   = (const float*)d_in[2];
    const float* bc   = (const float*)d_in[3];
    const float* Wout = (const float*)d_in[4];
    const float* bout = (const float*)d_in[5];
    float* out = (float*)d_out;

    const int B = in_sizes[0] / (LDIM * LDIM);
    rnn2d_kernel<<<B, 32>>>(x, Win, Wc, bc, Wout, bout, out);
}